// round 7
// baseline (speedup 1.0000x reference)
#include <cuda_runtime.h>
#include <cstdint>

#define B_EX   16384
#define NEG    10
#define WARPS_PER_BLOCK 8
#define THREADS (WARPS_PER_BLOCK * 32)
#define EX_PER_WARP 2
#define NBLOCKS (B_EX / (WARPS_PER_BLOCK * EX_PER_WARP))   // 1024
#define ROWS 11            // x + 10 noise rows staged in smem

// Scratch (allocation-free __device__ globals per harness rules)
__device__ float        g_partials[NBLOCKS];
__device__ unsigned int g_count = 0;

__device__ __forceinline__ float log_sigmoid(float x) {
    return fminf(x, 0.0f) - log1pf(expf(-fabsf(x)));
}

__device__ __forceinline__ float warp_sum(float v) {
#pragma unroll
    for (int off = 16; off > 0; off >>= 1)
        v += __shfl_xor_sync(0xffffffffu, v, off);
    return v;
}

__device__ __forceinline__ float dot4(float4 a, float4 b) {
    return a.x * b.x + a.y * b.y + a.z * b.z + a.w * b.w;
}

__device__ __forceinline__ void cp_async16(void* dst_smem, const void* src_gmem) {
    uint32_t d = (uint32_t)__cvta_generic_to_shared(dst_smem);
    asm volatile("cp.async.cg.shared.global [%0], [%1], 16;"
                 :: "r"(d), "l"(src_gmem));
}
#define CP_COMMIT()  asm volatile("cp.async.commit_group;" ::: "memory")
#define CP_WAIT(n)   asm volatile("cp.async.wait_group %0;" :: "n"(n) : "memory")

__global__ void __launch_bounds__(THREADS)
w2v_fused_kernel(const int*    __restrict__ input_word,
                 const int*    __restrict__ context_word,
                 const int*    __restrict__ noise_words,
                 const float4* __restrict__ W_in,
                 const float4* __restrict__ W_ctx,
                 float*        __restrict__ out)
{
    // [stage][warp][row][lane] : 2*8*11*32*16B = 45056 B
    __shared__ float4 buf[2][WARPS_PER_BLOCK][ROWS][32];
    __shared__ float  s_warp[WARPS_PER_BLOCK];
    __shared__ float  s_red[THREADS];
    __shared__ bool   s_is_last;

    const int lane    = threadIdx.x & 31;
    const int warp_in = threadIdx.x >> 5;
    const int b0      = (blockIdx.x * WARPS_PER_BLOCK + warp_in) * EX_PER_WARP;
    const int b1      = b0 + 1;

    // Uniform index loads (L1-broadcast within warp).
    const int ci0 = input_word[b0];
    const int ci1 = input_word[b1];
    const int xi0 = context_word[b0];
    const int xi1 = context_word[b1];
    int n0[NEG], n1[NEG];
#pragma unroll
    for (int k = 0; k < NEG; k++) n0[k] = noise_words[b0 * NEG + k];
#pragma unroll
    for (int k = 0; k < NEG; k++) n1[k] = noise_words[b1 * NEG + k];

    // ---- stage 0 prefetch: example b0 (11 rows via cp.async, c via LDG) ----
    float4 c0 = W_in[(size_t)ci0 * 32 + lane];
    cp_async16(&buf[0][warp_in][0][lane], &W_ctx[(size_t)xi0 * 32 + lane]);
#pragma unroll
    for (int k = 0; k < NEG; k++)
        cp_async16(&buf[0][warp_in][1 + k][lane], &W_ctx[(size_t)n0[k] * 32 + lane]);
    CP_COMMIT();

    // ---- stage 1 prefetch: example b1 ----
    float4 c1 = W_in[(size_t)ci1 * 32 + lane];
    cp_async16(&buf[1][warp_in][0][lane], &W_ctx[(size_t)xi1 * 32 + lane]);
#pragma unroll
    for (int k = 0; k < NEG; k++)
        cp_async16(&buf[1][warp_in][1 + k][lane], &W_ctx[(size_t)n1[k] * 32 + lane]);
    CP_COMMIT();

    // ---- compute example b0 (stage-1 loads still in flight underneath) ----
    CP_WAIT(1);   // lane reads exactly the bytes it copied -> no syncwarp needed
    float pos0 = dot4(c0, buf[0][warp_in][0][lane]);
    float s0[NEG];
#pragma unroll
    for (int k = 0; k < NEG; k++)
        s0[k] = dot4(c0, buf[0][warp_in][1 + k][lane]);

    pos0 = warp_sum(pos0);
#pragma unroll
    for (int k = 0; k < NEG; k++) s0[k] = warp_sum(s0[k]);
    float v0 = 0.0f;
    if (lane == 0) {
        v0 = -log_sigmoid(pos0);
#pragma unroll
        for (int k = 0; k < NEG; k++) v0 -= log_sigmoid(-s0[k]);
    }

    // ---- compute example b1 ----
    CP_WAIT(0);
    float pos1 = dot4(c1, buf[1][warp_in][0][lane]);
    float s1[NEG];
#pragma unroll
    for (int k = 0; k < NEG; k++)
        s1[k] = dot4(c1, buf[1][warp_in][1 + k][lane]);

    pos1 = warp_sum(pos1);
#pragma unroll
    for (int k = 0; k < NEG; k++) s1[k] = warp_sum(s1[k]);

    if (lane == 0) {
        float v1 = -log_sigmoid(pos1);
#pragma unroll
        for (int k = 0; k < NEG; k++) v1 -= log_sigmoid(-s1[k]);
        s_warp[warp_in] = v0 + v1;
    }
    __syncthreads();

    // ---- fused finalize: last block reduces all partials ----
    if (threadIdx.x == 0) {
        float t = 0.0f;
#pragma unroll
        for (int i = 0; i < WARPS_PER_BLOCK; i++) t += s_warp[i];
        g_partials[blockIdx.x] = t;
        unsigned int v;
        asm volatile("atom.release.gpu.global.add.u32 %0, [%1], 1;"
                     : "=r"(v) : "l"(&g_count) : "memory");
        s_is_last = (v == (unsigned int)(NBLOCKS - 1));
    }
    __syncthreads();

    if (s_is_last) {
        asm volatile("fence.acquire.gpu;" ::: "memory");
        volatile float* gp = g_partials;
        float t = 0.0f;
#pragma unroll
        for (int j = 0; j < NBLOCKS / THREADS; j++)     // 4 iterations
            t += gp[threadIdx.x + j * THREADS];

        s_red[threadIdx.x] = t;
        __syncthreads();
#pragma unroll
        for (int step = THREADS / 2; step > 0; step >>= 1) {
            if (threadIdx.x < step) s_red[threadIdx.x] += s_red[threadIdx.x + step];
            __syncthreads();
        }
        if (threadIdx.x == 0) {
            out[0]  = s_red[0] / (float)B_EX;
            g_count = 0;                   // reset for next graph replay
        }
    }
}

extern "C" void kernel_launch(void* const* d_in, const int* in_sizes, int n_in,
                              void* d_out, int out_size)
{
    const int*    input_word   = (const int*)   d_in[0];
    const int*    context_word = (const int*)   d_in[1];
    const int*    noise_words  = (const int*)   d_in[2];
    const float4* W_in         = (const float4*)d_in[3];
    const float4* W_ctx        = (const float4*)d_in[4];
    float* out = (float*)d_out;

    w2v_fused_kernel<<<NBLOCKS, THREADS>>>(input_word, context_word,
                                           noise_words, W_in, W_ctx, out);
}

// round 8
// speedup vs baseline: 1.5233x; 1.5233x over previous
#include <cuda_runtime.h>

#define B_EX   16384
#define NEG    10
#define NVAL   (NEG + 1)      // 11 partial values per example (pos + 10 neg)
#define WARPS_PER_BLOCK 8
#define THREADS (WARPS_PER_BLOCK * 32)
#define NBLOCKS (B_EX / WARPS_PER_BLOCK)   // 2048
#define NLOSS   (WARPS_PER_BLOCK * NVAL)   // 88 loss terms per block

// Scratch (allocation-free __device__ globals per harness rules)
__device__ float        g_partials[NBLOCKS];
__device__ unsigned int g_count = 0;

__device__ __forceinline__ float log_sigmoid(float x) {
    return fminf(x, 0.0f) - log1pf(expf(-fabsf(x)));
}

__device__ __forceinline__ float dot4(float4 a, float4 b) {
    return a.x * b.x + a.y * b.y + a.z * b.z + a.w * b.w;
}

__global__ void __launch_bounds__(THREADS)
w2v_fused_kernel(const int*    __restrict__ input_word,
                 const int*    __restrict__ context_word,
                 const int*    __restrict__ noise_words,
                 const float4* __restrict__ W_in,
                 const float4* __restrict__ W_ctx,
                 float*        __restrict__ out)
{
    // Per-lane partials, padded to 33 floats so the transposed read
    // (fixed j, thread-varying row) is bank-conflict-free.
    __shared__ float sp[WARPS_PER_BLOCK][NVAL][33];   // 11.6 KB
    __shared__ float s_vals[NLOSS];                   // 88 loss terms
    __shared__ bool  s_is_last;

    const int lane    = threadIdx.x & 31;
    const int warp_in = threadIdx.x >> 5;
    const int b       = blockIdx.x * WARPS_PER_BLOCK + warp_in;   // example id

    // Uniform (same-address) index loads: L1-broadcast within the warp.
    const int ci = input_word[b];
    const int xi = context_word[b];
    int nidx[NEG];
#pragma unroll
    for (int k = 0; k < NEG; k++) nidx[k] = noise_words[b * NEG + k];

    // Row = 128 floats = 32 float4; lane l owns float4 #l of each row.
    // All 12 gathers issued before any math for max MLP.
    float4 c = W_in [(size_t)ci * 32 + lane];
    float4 x = W_ctx[(size_t)xi * 32 + lane];
    float4 nv[NEG];
#pragma unroll
    for (int k = 0; k < NEG; k++)
        nv[k] = W_ctx[(size_t)nidx[k] * 32 + lane];

    // Per-lane partial dots -> smem (NO shuffle butterflies).
    sp[warp_in][0][lane] = dot4(c, x);
#pragma unroll
    for (int k = 0; k < NEG; k++)
        sp[warp_in][1 + k][lane] = dot4(c, nv[k]);
    __syncthreads();

    // 88 threads: each sums one (example, k) column of 32 partials
    // (fixed-order serial sum -> deterministic) and applies log-sigmoid.
    const int t = threadIdx.x;
    if (t < NLOSS) {
        const int ex = t / NVAL;
        const int k  = t % NVAL;
        float s = 0.0f;
#pragma unroll
        for (int j = 0; j < 32; j++)
            s += sp[ex][k][j];
        // pos term: -ls(s); neg terms: -ls(-s)
        s_vals[t] = (k == 0) ? -log_sigmoid(s) : -log_sigmoid(-s);
    }
    __syncthreads();

    // Warp 0 reduces the 88 loss terms (fixed order + butterfly: deterministic).
    if (warp_in == 0) {
        float v = 0.0f;
#pragma unroll
        for (int j = 0; j < 3; j++) {
            int idx = lane + j * 32;
            if (idx < NLOSS) v += s_vals[idx];
        }
#pragma unroll
        for (int off = 16; off > 0; off >>= 1)
            v += __shfl_xor_sync(0xffffffffu, v, off);

        if (lane == 0) {
            g_partials[blockIdx.x] = v;
            unsigned int cnt;
            asm volatile("atom.release.gpu.global.add.u32 %0, [%1], 1;"
                         : "=r"(cnt) : "l"(&g_count) : "memory");
            s_is_last = (cnt == (unsigned int)(NBLOCKS - 1));
        }
    }
    __syncthreads();

    // ---- fused finalize: last block reduces all block partials ----
    if (s_is_last) {
        asm volatile("fence.acquire.gpu;" ::: "memory");
        volatile float* gp = g_partials;
        float tacc = 0.0f;
#pragma unroll
        for (int j = 0; j < NBLOCKS / THREADS; j++)     // 8 iterations
            tacc += gp[threadIdx.x + j * THREADS];

        __shared__ float s_red[THREADS];
        s_red[threadIdx.x] = tacc;
        __syncthreads();
#pragma unroll
        for (int step = THREADS / 2; step > 0; step >>= 1) {
            if (threadIdx.x < step) s_red[threadIdx.x] += s_red[threadIdx.x + step];
            __syncthreads();
        }
        if (threadIdx.x == 0) {
            out[0]  = s_red[0] / (float)B_EX;
            g_count = 0;                   // reset for next graph replay
        }
    }
}

extern "C" void kernel_launch(void* const* d_in, const int* in_sizes, int n_in,
                              void* d_out, int out_size)
{
    const int*    input_word   = (const int*)   d_in[0];
    const int*    context_word = (const int*)   d_in[1];
    const int*    noise_words  = (const int*)   d_in[2];
    const float4* W_in         = (const float4*)d_in[3];
    const float4* W_ctx        = (const float4*)d_in[4];
    float* out = (float*)d_out;

    w2v_fused_kernel<<<NBLOCKS, THREADS>>>(input_word, context_word,
                                           noise_words, W_in, W_ctx, out);
}